// round 6
// baseline (speedup 1.0000x reference)
#include <cuda_runtime.h>

// ---------------- problem constants ----------------
#define NROWS     2048
#define RROWS     4
#define NTHREADS  512
#define SPONGE_N  1024
#define HALFW     512
#define QUARTW    256
#define ACT_N     256
#define DEPTH_N   8
#define BDEPTH_N  10
#define BF_SIZE   3072
#define BF_HALF   1536
#define BF_QUART  768
#define BF_DEPTH  12

#define SP_STRIDE   4624
#define MEM_OFF     (2*SP_STRIDE)        // 9248
#define BF_STRIDE   13840
#define SMEM_FLOATS (2*BF_STRIDE)        // 27680 floats = 110720 B

// ---------------- precomputed tables ----------------
__device__ __align__(16) float2 g_rot  [DEPTH_N*BDEPTH_N*HALFW];
__device__ __align__(16) float2 g_rp4  [DEPTH_N*2*64*32];   // packed sponge fused-4 coeffs
__device__ __align__(16) float2 g_bp4  [3*192*32];          // packed BF fused-4 coeffs
__device__ float4 g_act  [DEPTH_N*ACT_N];
__device__ int    g_recall[DEPTH_N*ACT_N];
__device__ int    g_outidx[2048];

__global__ void prep_kernel(const float* __restrict__ angles,
                            const float* __restrict__ act_bias,
                            const float* __restrict__ act_curv,
                            const void*  __restrict__ recall_raw,
                            const void*  __restrict__ out_raw)
{
    int i = blockIdx.x * blockDim.x + threadIdx.x;
    const int NROT = DEPTH_N*BDEPTH_N*HALFW;       // 40960
    if (i < NROT) {
        float s, c; sincosf(angles[i], &s, &c);
        g_rot[i] = make_float2(c, s);
    } else if (i < NROT + DEPTH_N*ACT_N) {
        int k = i - NROT;
        float cu = act_curv[k];
        float c  = 0.5f*(cu + sqrtf(cu*cu + 1.0f));
        g_act[k] = make_float4(act_bias[k], c, 0.25f*3.14159265358979323846f/c, 1.0f/c);
    }
    if (i < 2048) {
        const int* o32 = (const int*)out_raw;
        bool is64 = (o32[1]==0 && o32[3]==0 && o32[5]==0 && o32[7]==0);
        if (is64) {
            g_outidx[i] = (int)((const long long*)out_raw)[i];
            g_recall[i] = (int)((const long long*)recall_raw)[i];
        } else {
            g_outidx[i] = o32[i];
            g_recall[i] = ((const int*)recall_raw)[i];
        }
    }
}

// pack fused-4 coefficients: one thread per (stage-unit).
// order: j0..7   L1 k=0..7          idx = g + (S/8)k
//        j8..11  L2 a=0..3  (d=0)   idx = 2g + (S/4)a
//        j12..15 L2 a=8..11 (d=1)   idx = 2g + 1 + (S/4)(a-8)
//        j16..19 L3 (r,s)=(0,0),(0,1),(1,0),(1,1)  idx = 4g + r + (S/2)s
//        j20..23 L3 (2,0),(2,1),(3,0),(3,1)
//        j24..31 L4 q=0..7          idx = 8g + q
__device__ __forceinline__ void pack_unit(const float* ang, int S, int g, float2* dst)
{
    int j = 0;
    #pragma unroll
    for (int k = 0; k < 8; k++) {
        float s, c; sincosf(ang[g + (S/8)*k], &s, &c); dst[j++] = make_float2(c, s);
    }
    #pragma unroll
    for (int dd = 0; dd < 2; dd++)
        #pragma unroll
        for (int a = 0; a < 4; a++) {
            float s, c; sincosf(ang[S + 2*g + dd + (S/4)*a], &s, &c); dst[j++] = make_float2(c, s);
        }
    #pragma unroll
    for (int r = 0; r < 4; r++)
        #pragma unroll
        for (int ss = 0; ss < 2; ss++) {
            float s, c; sincosf(ang[2*S + 4*g + r + (S/2)*ss], &s, &c); dst[j++] = make_float2(c, s);
        }
    #pragma unroll
    for (int q = 0; q < 8; q++) {
        float s, c; sincosf(ang[3*S + 8*g + q], &s, &c); dst[j++] = make_float2(c, s);
    }
}

__global__ void prep2_kernel(const float* __restrict__ angles,
                             const float* __restrict__ bf_angles)
{
    int u = blockIdx.x * blockDim.x + threadIdx.x;
    if (u < DEPTH_N*2*64) {                      // sponge units
        int d  = u >> 7;
        int st = (u >> 6) & 1;
        int g  = u & 63;
        const float* ang = angles + (d*BDEPTH_N + 4*st)*HALFW;
        pack_unit(ang, HALFW, g, g_rp4 + u*32);
    } else if (u < DEPTH_N*2*64 + 3*192) {       // BF units
        int u2 = u - DEPTH_N*2*64;
        int st = u2 / 192;
        int g  = u2 % 192;
        const float* ang = bf_angles + (4*st)*BF_HALF;
        pack_unit(ang, BF_HALF, g, g_bp4 + u2*32);
    }
}

// ---------------- padded shared-memory indexing ----------------
__device__ __forceinline__ int isp(int p) { return 4*p + ((p>>3)<<2) + ((p>>9)<<4); }
__device__ __forceinline__ int ibf(int p) { return 4*p + ((p>>3)<<2) + ((p>=1536)?16:0); }

// fixed offsets (fused-2 sponge remainder; verified)
#define SR1 576
#define SR2 1152
#define SR3 1728
#define SW1 4
#define SW2 2320
#define SW3 2324

__device__ __forceinline__ float actf(float x, float c, float tt, float invc) {
    const float OOS2 = 0.70710678118654752f;
    float r = invc*(OOS2 - __cosf(0.78539816339744831f + c*x));
    if (x >  tt) r = invc*OOS2 + (x - tt);
    if (x < -tt) r = invc*(OOS2 - 1.0f);
    return r;
}

__device__ __forceinline__ float2 mix2(float c, float s, float2 a, float2 b) {
    return make_float2(c*a.x + s*b.x, c*a.y + s*b.y);
}

__device__ __forceinline__ void rot2(float2& p, float2& r, float2 cs) {
    float px = p.x, py = p.y;
    p.x = cs.x*px  + cs.y*r.x;  p.y = cs.x*py  + cs.y*r.y;
    r.x = cs.x*r.x - cs.y*px;   r.y = cs.x*r.y - cs.y*py;
}

// 4-layer fused butterfly for one unit (2 rows).
__device__ __forceinline__ void fused4(const float* __restrict__ IN,
                                       float* __restrict__ OUT,
                                       int rbase, int rstep, int wbase, int whi,
                                       const float4* __restrict__ cfp)
{
    // prefetch L1 coeffs + first halves' L2 early
    float4 cL1a = __ldg(cfp+0), cL1b = __ldg(cfp+1), cL1c = __ldg(cfp+2), cL1d = __ldg(cfp+3);
    float4 c2a  = __ldg(cfp+4), c2b  = __ldg(cfp+5);

    float2 v[16];
    #pragma unroll
    for (int k = 0; k < 16; k++) v[k] = *(const float2*)(IN + rbase + k*rstep);

    // L1: pairs (k, k+8)
    rot2(v[0], v[ 8], make_float2(cL1a.x, cL1a.y));
    rot2(v[1], v[ 9], make_float2(cL1a.z, cL1a.w));
    rot2(v[2], v[10], make_float2(cL1b.x, cL1b.y));
    rot2(v[3], v[11], make_float2(cL1b.z, cL1b.w));
    rot2(v[4], v[12], make_float2(cL1c.x, cL1c.y));
    rot2(v[5], v[13], make_float2(cL1c.z, cL1c.w));
    rot2(v[6], v[14], make_float2(cL1d.x, cL1d.y));
    rot2(v[7], v[15], make_float2(cL1d.z, cL1d.w));

    // ---- half 0 (regs 0..7): L2 a=0..3, L3 n=0,1,4,5, L4 q=0..3 ----
    float4 c3a = __ldg(cfp+8), c3b = __ldg(cfp+9);
    rot2(v[0], v[4], make_float2(c2a.x, c2a.y));
    rot2(v[1], v[5], make_float2(c2a.z, c2a.w));
    rot2(v[2], v[6], make_float2(c2b.x, c2b.y));
    rot2(v[3], v[7], make_float2(c2b.z, c2b.w));
    float4 c4a = __ldg(cfp+12), c4b = __ldg(cfp+13);
    rot2(v[0], v[2], make_float2(c3a.x, c3a.y));
    rot2(v[1], v[3], make_float2(c3a.z, c3a.w));
    rot2(v[4], v[6], make_float2(c3b.x, c3b.y));
    rot2(v[5], v[7], make_float2(c3b.z, c3b.w));
    float4 c2c = __ldg(cfp+6), c2d = __ldg(cfp+7);    // L2 half1
    rot2(v[0], v[1], make_float2(c4a.x, c4a.y));
    rot2(v[2], v[3], make_float2(c4a.z, c4a.w));
    rot2(v[4], v[5], make_float2(c4b.x, c4b.y));
    rot2(v[6], v[7], make_float2(c4b.z, c4b.w));
    *(float2*)(OUT + wbase +  0)       = v[0];
    *(float2*)(OUT + wbase +  0 + whi) = v[1];
    *(float2*)(OUT + wbase +  4)       = v[2];
    *(float2*)(OUT + wbase +  4 + whi) = v[3];
    *(float2*)(OUT + wbase +  8)       = v[4];
    *(float2*)(OUT + wbase +  8 + whi) = v[5];
    *(float2*)(OUT + wbase + 12)       = v[6];
    *(float2*)(OUT + wbase + 12 + whi) = v[7];

    // ---- half 1 (regs 8..15): L2 a=8..11, L3 n=8,9,12,13, L4 q=4..7 ----
    float4 c3c = __ldg(cfp+10), c3d = __ldg(cfp+11);
    rot2(v[ 8], v[12], make_float2(c2c.x, c2c.y));
    rot2(v[ 9], v[13], make_float2(c2c.z, c2c.w));
    rot2(v[10], v[14], make_float2(c2d.x, c2d.y));
    rot2(v[11], v[15], make_float2(c2d.z, c2d.w));
    float4 c4c = __ldg(cfp+14), c4d = __ldg(cfp+15);
    rot2(v[ 8], v[10], make_float2(c3c.x, c3c.y));
    rot2(v[ 9], v[11], make_float2(c3c.z, c3c.w));
    rot2(v[12], v[14], make_float2(c3d.x, c3d.y));
    rot2(v[13], v[15], make_float2(c3d.z, c3d.w));
    rot2(v[ 8], v[ 9], make_float2(c4c.x, c4c.y));
    rot2(v[10], v[11], make_float2(c4c.z, c4c.w));
    rot2(v[12], v[13], make_float2(c4d.x, c4d.y));
    rot2(v[14], v[15], make_float2(c4d.z, c4d.w));
    *(float2*)(OUT + wbase + 16)       = v[ 8];
    *(float2*)(OUT + wbase + 16 + whi) = v[ 9];
    *(float2*)(OUT + wbase + 20)       = v[10];
    *(float2*)(OUT + wbase + 20 + whi) = v[11];
    *(float2*)(OUT + wbase + 24)       = v[12];
    *(float2*)(OUT + wbase + 24 + whi) = v[13];
    *(float2*)(OUT + wbase + 28)       = v[14];
    *(float2*)(OUT + wbase + 28 + whi) = v[15];
}

__global__ void __launch_bounds__(NTHREADS, 2)
sponge_kernel(const float* __restrict__ X,
              const float* __restrict__ scales,
              float* __restrict__ out)
{
    extern __shared__ float sb[];
    const int t    = threadIdx.x;
    const int row0 = blockIdx.x * RROWS;
    float* const MEMB = sb + MEM_OFF;

    // ---- load X * scales into sponge buffer 0 ----
    {
        float sc0 = scales[t], sc1 = scales[t + HALFW];
        int i0 = isp(t), i1 = i0 + SW2;
        #pragma unroll
        for (int r = 0; r < RROWS; r++) {
            const float* xr = X + (size_t)(row0 + r) * SPONGE_N;
            sb[i0 + r] = xr[t]         * sc0;
            sb[i1 + r] = xr[t + HALFW] * sc1;
        }
    }
    __syncthreads();

    // fused-2 remainder constants (sponge layers 8,9)
    const int  m   = t >> 1;
    const int  rh  = t & 1;
    const bool odd = rh;
    const int  A1  = (m >> 1) + (m & 1) * HALFW;
    const int  rb  = isp(A1)  + 2*rh;
    const int  wb  = isp(2*m) + 2*rh;
    const int  w0  = isp(t);
    const int  w1  = w0 + SW2;

    // fused-4 sponge constants (active threads t<128)
    const int g4s = t >> 1;            // unit (valid when t<128)
    const int h4s = g4s >> 1;
    const int e4s = g4s & 1;
    const int rb4s = 4*h4s + ((h4s>>3)<<2) + 2320*e4s + 2*rh;
    const int wb4s = 36*g4s + 2*rh;

    int cur = 0;
    for (int d = 0; d < DEPTH_N; d++) {
        // ---- two fused-4 stages (layers 0-3, 4-7) ----
        #pragma unroll
        for (int st = 0; st < 2; st++) {
            if (t < 128) {
                const float4* cfp = (const float4*)(g_rp4 + ((d*2 + st)*64 + g4s)*32);
                fused4(sb + cur*SP_STRIDE, sb + (cur^1)*SP_STRIDE,
                       rb4s, 144, wb4s, 2320, cfp);
            }
            cur ^= 1;
            __syncthreads();
        }

        // ---- fused-2 remainder (layers 8,9) ----
        {
            const float2* rotd = g_rot + d*(BDEPTH_N*HALFW);
            const float2* r0 = rotd + 8*HALFW;
            float2 cs1 = r0[m];
            float2 cs2 = r0[m + QUARTW];
            float4 co4 = ((const float4*)(rotd + 9*HALFW))[m];
            const float* IN  = sb + cur*SP_STRIDE;
            float*       OUT = sb + (cur^1)*SP_STRIDE;

            float2 a1 = *(const float2*)(IN + rb);
            float2 a2 = *(const float2*)(IN + rb + SR1);
            float2 b1 = *(const float2*)(IN + rb + SR2);
            float2 b2 = *(const float2*)(IN + rb + SR3);
            float2 y1e = mix2(cs1.x,  cs1.y, a1, b1);
            float2 y1o = mix2(cs1.x, -cs1.y, b1, a1);
            float2 y2e = mix2(cs2.x,  cs2.y, a2, b2);
            float2 y2o = mix2(cs2.x, -cs2.y, b2, a2);
            *(float2*)(OUT + wb)       = mix2(co4.x,  co4.y, y1e, y2e);
            *(float2*)(OUT + wb + SW1) = mix2(co4.z,  co4.w, y1o, y2o);
            *(float2*)(OUT + wb + SW2) = mix2(co4.x, -co4.y, y2e, y1e);
            *(float2*)(OUT + wb + SW3) = mix2(co4.z, -co4.w, y2o, y1o);
            cur ^= 1;
            __syncthreads();
        }
        float* S = sb + cur*SP_STRIDE;

        // ---- activation / mem store / recall ----
        int ja = t >> 1;
        float4 ap = g_act[d*ACT_N + ja];
        float4 x  = *(const float4*)(S + isp(HALFW + ja));
        float sg  = odd ? -1.0f : 1.0f;
        float4 o;
        o.x = actf(sg*(x.x + ap.x), ap.y, ap.z, ap.w);
        o.y = actf(sg*(x.y + ap.x), ap.y, ap.z, ap.w);
        o.z = actf(sg*(x.z + ap.x), ap.y, ap.z, ap.w);
        o.w = actf(sg*(x.w + ap.x), ap.y, ap.z, ap.w);

        float4 mv = *(const float4*)(S + w0);
        *(float4*)(MEMB + (d*HALFW + t)*RROWS) = mv;

        float4 kv = make_float4(0.f,0.f,0.f,0.f);
        if (t < QUARTW) kv = *(const float4*)(S + isp(3*QUARTW + t));
        __syncthreads();

        *(float4*)(S + w0) = o;
        if (t < QUARTW) {
            *(float4*)(S + isp(HALFW + t)) = kv;
        } else {
            int q  = t - QUARTW;
            int mi = g_recall[d*ACT_N + q];
            *(float4*)(S + isp(3*QUARTW + q)) = *(const float4*)(MEMB + mi*RROWS);
        }
        __syncthreads();
    }
    // per depth: 3 flips (odd) x 8 depths = 24 flips -> sponge in buffer 0

    // ---- build pre = [mem[out_idx] (2048), sponge (1024)] in BF buffer 0 ----
    {
        float4 s0 = *(const float4*)(sb + w0);
        float4 s1 = *(const float4*)(sb + w1);
        __syncthreads();
        #pragma unroll
        for (int p = 0; p < 2048; p += NTHREADS) {
            int pp = p + t;
            int oi = g_outidx[pp];
            *(float4*)(sb + ibf(pp)) = *(const float4*)(MEMB + oi*RROWS);
        }
        __syncthreads();
        *(float4*)(sb + ibf(2048 + t))         = s0;
        *(float4*)(sb + ibf(2048 + HALFW + t)) = s1;
        __syncthreads();
    }

    // ---- final butterfly: 12 layers = 3 fused-4 stages (384 active threads) ----
    {
        const int g4 = t >> 1;            // unit (valid when t<384)
        const int h4 = g4 >> 1;
        const int e4 = g4 & 1;
        const int rb4 = 4*h4 + ((h4>>3)<<2) + 6928*e4 + 2*rh;
        const int wb4 = 36*g4 + 2*rh;

        int c2 = 0;
        #pragma unroll
        for (int st = 0; st < 3; st++) {
            if (t < 384) {
                const float4* cfp = (const float4*)(g_bp4 + (st*192 + g4)*32);
                fused4(sb + c2*BF_STRIDE, sb + (c2^1)*BF_STRIDE,
                       rb4, 432, wb4, 6928, cfp);
            }
            c2 ^= 1;
            __syncthreads();
        }
    }

    // result in buffer 1 (3 flips); emit first 512 columns
    {
        float4 v = *(const float4*)(sb + BF_STRIDE + ibf(t));
        out[(size_t)(row0 + 0)*HALFW + t] = v.x;
        out[(size_t)(row0 + 1)*HALFW + t] = v.y;
        out[(size_t)(row0 + 2)*HALFW + t] = v.z;
        out[(size_t)(row0 + 3)*HALFW + t] = v.w;
    }
}

extern "C" void kernel_launch(void* const* d_in, const int* in_sizes, int n_in,
                              void* d_out, int out_size)
{
    (void)in_sizes; (void)n_in; (void)out_size;
    const float* X          = (const float*)d_in[0];
    const float* scales     = (const float*)d_in[1];
    const float* angles     = (const float*)d_in[2];
    const float* act_bias   = (const float*)d_in[3];
    // d_in[4] = act_activation (unused by reference)
    const float* act_curv   = (const float*)d_in[5];
    const float* bf_angles  = (const float*)d_in[6];
    // d_in[7] = shuffle_perm (deterministic riffle, computed inline)
    const void*  recall_raw = d_in[8];
    const void*  out_raw    = d_in[9];
    // d_in[10] = bf_perm (deterministic riffle, computed inline)
    float* out = (float*)d_out;

    const int totalPrep = DEPTH_N*BDEPTH_N*HALFW + DEPTH_N*ACT_N;
    prep_kernel<<<(totalPrep + 255)/256, 256>>>(angles, act_bias, act_curv,
                                                recall_raw, out_raw);
    const int totalUnits = DEPTH_N*2*64 + 3*192;  // 1600
    prep2_kernel<<<(totalUnits + 255)/256, 256>>>(angles, bf_angles);

    size_t smem = SMEM_FLOATS * sizeof(float);
    cudaFuncSetAttribute(sponge_kernel, cudaFuncAttributeMaxDynamicSharedMemorySize, (int)smem);
    sponge_kernel<<<NROWS/RROWS, NTHREADS, smem>>>(X, scales, out);
}

// round 7
// speedup vs baseline: 1.0006x; 1.0006x over previous
#include <cuda_runtime.h>

// ---------------- problem constants ----------------
#define NROWS     2048
#define RROWS     4
#define NTHREADS  512
#define SPONGE_N  1024
#define HALFW     512
#define QUARTW    256
#define ACT_N     256
#define DEPTH_N   8
#define BDEPTH_N  10
#define BF_SIZE   3072
#define BF_HALF   1536
#define BF_QUART  768
#define BF_DEPTH  12

#define SP_STRIDE   4624
#define MEM_OFF     (2*SP_STRIDE)        // 9248
#define BF_STRIDE   13840
#define SMEM_FLOATS (2*BF_STRIDE)        // 27680 floats = 110720 B

// ---------------- precomputed tables ----------------
__device__ __align__(16) float2 g_rot  [DEPTH_N*BDEPTH_N*HALFW];
__device__ __align__(16) float2 g_rp4  [DEPTH_N*2*64*32];   // packed sponge fused-4 coeffs
__device__ __align__(16) float2 g_bp4  [3*192*32];          // packed BF fused-4 coeffs
__device__ float4 g_act  [DEPTH_N*ACT_N];
__device__ int    g_recall[DEPTH_N*ACT_N];
__device__ int    g_outidx[2048];

__global__ void prep_kernel(const float* __restrict__ angles,
                            const float* __restrict__ act_bias,
                            const float* __restrict__ act_curv,
                            const void*  __restrict__ recall_raw,
                            const void*  __restrict__ out_raw)
{
    int i = blockIdx.x * blockDim.x + threadIdx.x;
    const int NROT = DEPTH_N*BDEPTH_N*HALFW;
    if (i < NROT) {
        float s, c; sincosf(angles[i], &s, &c);
        g_rot[i] = make_float2(c, s);
    } else if (i < NROT + DEPTH_N*ACT_N) {
        int k = i - NROT;
        float cu = act_curv[k];
        float c  = 0.5f*(cu + sqrtf(cu*cu + 1.0f));
        g_act[k] = make_float4(act_bias[k], c, 0.25f*3.14159265358979323846f/c, 1.0f/c);
    }
    if (i < 2048) {
        const int* o32 = (const int*)out_raw;
        bool is64 = (o32[1]==0 && o32[3]==0 && o32[5]==0 && o32[7]==0);
        if (is64) {
            g_outidx[i] = (int)((const long long*)out_raw)[i];
            g_recall[i] = (int)((const long long*)recall_raw)[i];
        } else {
            g_outidx[i] = o32[i];
            g_recall[i] = ((const int*)recall_raw)[i];
        }
    }
}

// pack fused-4 coefficients (order matches fused4 consumption; verified in R6)
__device__ __forceinline__ void pack_unit(const float* ang, int S, int g, float2* dst)
{
    int j = 0;
    #pragma unroll
    for (int k = 0; k < 8; k++) {
        float s, c; sincosf(ang[g + (S/8)*k], &s, &c); dst[j++] = make_float2(c, s);
    }
    #pragma unroll
    for (int dd = 0; dd < 2; dd++)
        #pragma unroll
        for (int a = 0; a < 4; a++) {
            float s, c; sincosf(ang[S + 2*g + dd + (S/4)*a], &s, &c); dst[j++] = make_float2(c, s);
        }
    #pragma unroll
    for (int r = 0; r < 4; r++)
        #pragma unroll
        for (int ss = 0; ss < 2; ss++) {
            float s, c; sincosf(ang[2*S + 4*g + r + (S/2)*ss], &s, &c); dst[j++] = make_float2(c, s);
        }
    #pragma unroll
    for (int q = 0; q < 8; q++) {
        float s, c; sincosf(ang[3*S + 8*g + q], &s, &c); dst[j++] = make_float2(c, s);
    }
}

__global__ void prep2_kernel(const float* __restrict__ angles,
                             const float* __restrict__ bf_angles)
{
    int u = blockIdx.x * blockDim.x + threadIdx.x;
    if (u < DEPTH_N*2*64) {
        int d  = u >> 7;
        int st = (u >> 6) & 1;
        int g  = u & 63;
        const float* ang = angles + (d*BDEPTH_N + 4*st)*HALFW;
        pack_unit(ang, HALFW, g, g_rp4 + u*32);
    } else if (u < DEPTH_N*2*64 + 3*192) {
        int u2 = u - DEPTH_N*2*64;
        int st = u2 / 192;
        int g  = u2 % 192;
        const float* ang = bf_angles + (4*st)*BF_HALF;
        pack_unit(ang, BF_HALF, g, g_bp4 + u2*32);
    }
}

// ---------------- padded shared-memory indexing ----------------
__device__ __forceinline__ int isp(int p) { return 4*p + ((p>>3)<<2) + ((p>>9)<<4); }
__device__ __forceinline__ int ibf(int p) { return 4*p + ((p>>3)<<2) + ((p>=1536)?16:0); }

// fused-2 sponge remainder fixed offsets (verified)
#define SR1 576
#define SR2 1152
#define SR3 1728
#define SW1 4
#define SW2 2320
#define SW3 2324

__device__ __forceinline__ float actf(float x, float c, float tt, float invc) {
    const float OOS2 = 0.70710678118654752f;
    float r = invc*(OOS2 - __cosf(0.78539816339744831f + c*x));
    if (x >  tt) r = invc*OOS2 + (x - tt);
    if (x < -tt) r = invc*(OOS2 - 1.0f);
    return r;
}

__device__ __forceinline__ float2 mix2(float c, float s, float2 a, float2 b) {
    return make_float2(c*a.x + s*b.x, c*a.y + s*b.y);
}

__device__ __forceinline__ void rot2(float2& p, float2& r, float2 cs) {
    float px = p.x, py = p.y;
    p.x = cs.x*px  + cs.y*r.x;  p.y = cs.x*py  + cs.y*r.y;
    r.x = cs.x*r.x - cs.y*px;   r.y = cs.x*r.y - cs.y*py;
}

__device__ __forceinline__ void rot2s(float& p, float& r, float c, float s) {
    float px = p;
    p = c*px + s*r;
    r = c*r  - s*px;
}

// 4-layer fused butterfly, SCALAR version: one thread = one unit, one row.
__device__ __forceinline__ void fused4s(const float* __restrict__ IN,
                                        float* __restrict__ OUT,
                                        int rbase, int rstep, int wbase, int whi,
                                        const float4* __restrict__ cfp)
{
    float4 cL1a = __ldg(cfp+0), cL1b = __ldg(cfp+1), cL1c = __ldg(cfp+2), cL1d = __ldg(cfp+3);
    float4 c2a  = __ldg(cfp+4), c2b  = __ldg(cfp+5);

    float v[16];
    #pragma unroll
    for (int k = 0; k < 16; k++) v[k] = IN[rbase + k*rstep];

    rot2s(v[0], v[ 8], cL1a.x, cL1a.y);
    rot2s(v[1], v[ 9], cL1a.z, cL1a.w);
    rot2s(v[2], v[10], cL1b.x, cL1b.y);
    rot2s(v[3], v[11], cL1b.z, cL1b.w);
    rot2s(v[4], v[12], cL1c.x, cL1c.y);
    rot2s(v[5], v[13], cL1c.z, cL1c.w);
    rot2s(v[6], v[14], cL1d.x, cL1d.y);
    rot2s(v[7], v[15], cL1d.z, cL1d.w);

    float4 c3a = __ldg(cfp+8), c3b = __ldg(cfp+9);
    rot2s(v[0], v[4], c2a.x, c2a.y);
    rot2s(v[1], v[5], c2a.z, c2a.w);
    rot2s(v[2], v[6], c2b.x, c2b.y);
    rot2s(v[3], v[7], c2b.z, c2b.w);
    float4 c4a = __ldg(cfp+12), c4b = __ldg(cfp+13);
    rot2s(v[0], v[2], c3a.x, c3a.y);
    rot2s(v[1], v[3], c3a.z, c3a.w);
    rot2s(v[4], v[6], c3b.x, c3b.y);
    rot2s(v[5], v[7], c3b.z, c3b.w);
    float4 c2c = __ldg(cfp+6), c2d = __ldg(cfp+7);
    rot2s(v[0], v[1], c4a.x, c4a.y);
    rot2s(v[2], v[3], c4a.z, c4a.w);
    rot2s(v[4], v[5], c4b.x, c4b.y);
    rot2s(v[6], v[7], c4b.z, c4b.w);
    OUT[wbase +  0]       = v[0];
    OUT[wbase +  0 + whi] = v[1];
    OUT[wbase +  4]       = v[2];
    OUT[wbase +  4 + whi] = v[3];
    OUT[wbase +  8]       = v[4];
    OUT[wbase +  8 + whi] = v[5];
    OUT[wbase + 12]       = v[6];
    OUT[wbase + 12 + whi] = v[7];

    float4 c3c = __ldg(cfp+10), c3d = __ldg(cfp+11);
    rot2s(v[ 8], v[12], c2c.x, c2c.y);
    rot2s(v[ 9], v[13], c2c.z, c2c.w);
    rot2s(v[10], v[14], c2d.x, c2d.y);
    rot2s(v[11], v[15], c2d.z, c2d.w);
    float4 c4c = __ldg(cfp+14), c4d = __ldg(cfp+15);
    rot2s(v[ 8], v[10], c3c.x, c3c.y);
    rot2s(v[ 9], v[11], c3c.z, c3c.w);
    rot2s(v[12], v[14], c3d.x, c3d.y);
    rot2s(v[13], v[15], c3d.z, c3d.w);
    rot2s(v[ 8], v[ 9], c4c.x, c4c.y);
    rot2s(v[10], v[11], c4c.z, c4c.w);
    rot2s(v[12], v[13], c4d.x, c4d.y);
    rot2s(v[14], v[15], c4d.z, c4d.w);
    OUT[wbase + 16]       = v[ 8];
    OUT[wbase + 16 + whi] = v[ 9];
    OUT[wbase + 20]       = v[10];
    OUT[wbase + 20 + whi] = v[11];
    OUT[wbase + 24]       = v[12];
    OUT[wbase + 24 + whi] = v[13];
    OUT[wbase + 28]       = v[14];
    OUT[wbase + 28 + whi] = v[15];
}

// 4-layer fused butterfly, float2 version (BF; verified in R6)
__device__ __forceinline__ void fused4(const float* __restrict__ IN,
                                       float* __restrict__ OUT,
                                       int rbase, int rstep, int wbase, int whi,
                                       const float4* __restrict__ cfp)
{
    float4 cL1a = __ldg(cfp+0), cL1b = __ldg(cfp+1), cL1c = __ldg(cfp+2), cL1d = __ldg(cfp+3);
    float4 c2a  = __ldg(cfp+4), c2b  = __ldg(cfp+5);

    float2 v[16];
    #pragma unroll
    for (int k = 0; k < 16; k++) v[k] = *(const float2*)(IN + rbase + k*rstep);

    rot2(v[0], v[ 8], make_float2(cL1a.x, cL1a.y));
    rot2(v[1], v[ 9], make_float2(cL1a.z, cL1a.w));
    rot2(v[2], v[10], make_float2(cL1b.x, cL1b.y));
    rot2(v[3], v[11], make_float2(cL1b.z, cL1b.w));
    rot2(v[4], v[12], make_float2(cL1c.x, cL1c.y));
    rot2(v[5], v[13], make_float2(cL1c.z, cL1c.w));
    rot2(v[6], v[14], make_float2(cL1d.x, cL1d.y));
    rot2(v[7], v[15], make_float2(cL1d.z, cL1d.w));

    float4 c3a = __ldg(cfp+8), c3b = __ldg(cfp+9);
    rot2(v[0], v[4], make_float2(c2a.x, c2a.y));
    rot2(v[1], v[5], make_float2(c2a.z, c2a.w));
    rot2(v[2], v[6], make_float2(c2b.x, c2b.y));
    rot2(v[3], v[7], make_float2(c2b.z, c2b.w));
    float4 c4a = __ldg(cfp+12), c4b = __ldg(cfp+13);
    rot2(v[0], v[2], make_float2(c3a.x, c3a.y));
    rot2(v[1], v[3], make_float2(c3a.z, c3a.w));
    rot2(v[4], v[6], make_float2(c3b.x, c3b.y));
    rot2(v[5], v[7], make_float2(c3b.z, c3b.w));
    float4 c2c = __ldg(cfp+6), c2d = __ldg(cfp+7);
    rot2(v[0], v[1], make_float2(c4a.x, c4a.y));
    rot2(v[2], v[3], make_float2(c4a.z, c4a.w));
    rot2(v[4], v[5], make_float2(c4b.x, c4b.y));
    rot2(v[6], v[7], make_float2(c4b.z, c4b.w));
    *(float2*)(OUT + wbase +  0)       = v[0];
    *(float2*)(OUT + wbase +  0 + whi) = v[1];
    *(float2*)(OUT + wbase +  4)       = v[2];
    *(float2*)(OUT + wbase +  4 + whi) = v[3];
    *(float2*)(OUT + wbase +  8)       = v[4];
    *(float2*)(OUT + wbase +  8 + whi) = v[5];
    *(float2*)(OUT + wbase + 12)       = v[6];
    *(float2*)(OUT + wbase + 12 + whi) = v[7];

    float4 c3c = __ldg(cfp+10), c3d = __ldg(cfp+11);
    rot2(v[ 8], v[12], make_float2(c2c.x, c2c.y));
    rot2(v[ 9], v[13], make_float2(c2c.z, c2c.w));
    rot2(v[10], v[14], make_float2(c2d.x, c2d.y));
    rot2(v[11], v[15], make_float2(c2d.z, c2d.w));
    float4 c4c = __ldg(cfp+14), c4d = __ldg(cfp+15);
    rot2(v[ 8], v[10], make_float2(c3c.x, c3c.y));
    rot2(v[ 9], v[11], make_float2(c3c.z, c3c.w));
    rot2(v[12], v[14], make_float2(c3d.x, c3d.y));
    rot2(v[13], v[15], make_float2(c3d.z, c3d.w));
    rot2(v[ 8], v[ 9], make_float2(c4c.x, c4c.y));
    rot2(v[10], v[11], make_float2(c4c.z, c4c.w));
    rot2(v[12], v[13], make_float2(c4d.x, c4d.y));
    rot2(v[14], v[15], make_float2(c4d.z, c4d.w));
    *(float2*)(OUT + wbase + 16)       = v[ 8];
    *(float2*)(OUT + wbase + 16 + whi) = v[ 9];
    *(float2*)(OUT + wbase + 20)       = v[10];
    *(float2*)(OUT + wbase + 20 + whi) = v[11];
    *(float2*)(OUT + wbase + 24)       = v[12];
    *(float2*)(OUT + wbase + 24 + whi) = v[13];
    *(float2*)(OUT + wbase + 28)       = v[14];
    *(float2*)(OUT + wbase + 28 + whi) = v[15];
}

__global__ void __launch_bounds__(NTHREADS, 2)
sponge_kernel(const float* __restrict__ X,
              const float* __restrict__ scales,
              float* __restrict__ out)
{
    extern __shared__ float sb[];
    const int t    = threadIdx.x;
    const int row0 = blockIdx.x * RROWS;
    float* const MEMB = sb + MEM_OFF;

    // ---- load X * scales into sponge buffer 0 ----
    {
        float sc0 = scales[t], sc1 = scales[t + HALFW];
        int i0 = isp(t), i1 = i0 + SW2;
        #pragma unroll
        for (int r = 0; r < RROWS; r++) {
            const float* xr = X + (size_t)(row0 + r) * SPONGE_N;
            sb[i0 + r] = xr[t]         * sc0;
            sb[i1 + r] = xr[t + HALFW] * sc1;
        }
    }
    __syncthreads();

    // fused-2 remainder constants (layers 8,9)
    const int  m   = t >> 1;
    const int  rh  = t & 1;
    const bool odd = rh;
    const int  A1  = (m >> 1) + (m & 1) * HALFW;
    const int  rb  = isp(A1)  + 2*rh;
    const int  wb  = isp(2*m) + 2*rh;
    const int  w0  = isp(t);
    const int  w1  = w0 + SW2;

    // fused-4 sponge constants: thread = (unit g4 in [0,64), row r4), active t<256
    const int g4s = t >> 2;
    const int r4  = t & 3;
    const int h4s = g4s >> 1;
    const int e4s = g4s & 1;
    const int rb4s = 4*h4s + ((h4s>>3)<<2) + 2320*e4s + r4;
    const int wb4s = 36*g4s + r4;

    int cur = 0;
    for (int d = 0; d < DEPTH_N; d++) {
        // ---- two fused-4 stages (layers 0-3, 4-7), 256 active threads ----
        #pragma unroll
        for (int st = 0; st < 2; st++) {
            if (t < 256) {
                const float4* cfp = (const float4*)(g_rp4 + ((d*2 + st)*64 + g4s)*32);
                fused4s(sb + cur*SP_STRIDE, sb + (cur^1)*SP_STRIDE,
                        rb4s, 144, wb4s, 2320, cfp);
            }
            cur ^= 1;
            __syncthreads();
        }

        // ---- fused-2 remainder (layers 8,9), 512 threads ----
        {
            const float2* rotd = g_rot + d*(BDEPTH_N*HALFW);
            const float2* r0 = rotd + 8*HALFW;
            float2 cs1 = r0[m];
            float2 cs2 = r0[m + QUARTW];
            float4 co4 = ((const float4*)(rotd + 9*HALFW))[m];
            const float* IN  = sb + cur*SP_STRIDE;
            float*       OUT = sb + (cur^1)*SP_STRIDE;

            float2 a1 = *(const float2*)(IN + rb);
            float2 a2 = *(const float2*)(IN + rb + SR1);
            float2 b1 = *(const float2*)(IN + rb + SR2);
            float2 b2 = *(const float2*)(IN + rb + SR3);
            float2 y1e = mix2(cs1.x,  cs1.y, a1, b1);
            float2 y1o = mix2(cs1.x, -cs1.y, b1, a1);
            float2 y2e = mix2(cs2.x,  cs2.y, a2, b2);
            float2 y2o = mix2(cs2.x, -cs2.y, b2, a2);
            *(float2*)(OUT + wb)       = mix2(co4.x,  co4.y, y1e, y2e);
            *(float2*)(OUT + wb + SW1) = mix2(co4.z,  co4.w, y1o, y2o);
            *(float2*)(OUT + wb + SW2) = mix2(co4.x, -co4.y, y2e, y1e);
            *(float2*)(OUT + wb + SW3) = mix2(co4.z, -co4.w, y2o, y1o);
            cur ^= 1;
            __syncthreads();
        }

        // ---- activation / mem store / recall: ONE barrier, writes to OUT buffer ----
        {
            const float* S    = sb + cur*SP_STRIDE;
            float*       OUTB = sb + (cur^1)*SP_STRIDE;
            int ja = t >> 1;
            float4 ap = g_act[d*ACT_N + ja];
            float4 x  = *(const float4*)(S + isp(HALFW + ja));
            float sg  = odd ? -1.0f : 1.0f;
            float4 o;
            o.x = actf(sg*(x.x + ap.x), ap.y, ap.z, ap.w);
            o.y = actf(sg*(x.y + ap.x), ap.y, ap.z, ap.w);
            o.z = actf(sg*(x.z + ap.x), ap.y, ap.z, ap.w);
            o.w = actf(sg*(x.w + ap.x), ap.y, ap.z, ap.w);

            // mem store for this depth (readers this depth are redirected to S)
            float4 mv = *(const float4*)(S + w0);
            *(float4*)(MEMB + (d*HALFW + t)*RROWS) = mv;

            *(float4*)(OUTB + w0) = o;                        // act_out -> [0,512)
            if (t < QUARTW) {
                float4 kv = *(const float4*)(S + isp(3*QUARTW + t));
                *(float4*)(OUTB + isp(HALFW + t)) = kv;       // [768,1024) -> [512,768)
            } else {
                int q  = t - QUARTW;
                int mi = g_recall[d*ACT_N + q];
                float4 rv = (mi >= d*HALFW)
                    ? *(const float4*)(S + isp(mi - d*HALFW))
                    : *(const float4*)(MEMB + mi*RROWS);
                *(float4*)(OUTB + isp(3*QUARTW + q)) = rv;    // recall -> [768,1024)
            }
            cur ^= 1;
            __syncthreads();
        }
    }
    // per depth: 4 flips -> cur returns to 0 each depth; sponge in buffer 0

    // ---- build pre = [mem[out_idx] (2048), sponge (1024)] in BF buffer 0 ----
    {
        float4 s0 = *(const float4*)(sb + w0);
        float4 s1 = *(const float4*)(sb + w1);
        __syncthreads();
        #pragma unroll
        for (int p = 0; p < 2048; p += NTHREADS) {
            int pp = p + t;
            int oi = g_outidx[pp];
            *(float4*)(sb + ibf(pp)) = *(const float4*)(MEMB + oi*RROWS);
        }
        __syncthreads();
        *(float4*)(sb + ibf(2048 + t))         = s0;
        *(float4*)(sb + ibf(2048 + HALFW + t)) = s1;
        __syncthreads();
    }

    // ---- final butterfly: 12 layers = 3 fused-4 stages (384 active threads) ----
    {
        const int g4 = t >> 1;            // unit (valid when t<384)
        const int h4 = g4 >> 1;
        const int e4 = g4 & 1;
        const int rb4 = 4*h4 + ((h4>>3)<<2) + 6928*e4 + 2*rh;
        const int wb4 = 36*g4 + 2*rh;

        int c2 = 0;
        #pragma unroll
        for (int st = 0; st < 3; st++) {
            if (t < 384) {
                const float4* cfp = (const float4*)(g_bp4 + (st*192 + g4)*32);
                fused4(sb + c2*BF_STRIDE, sb + (c2^1)*BF_STRIDE,
                       rb4, 432, wb4, 6928, cfp);
            }
            c2 ^= 1;
            __syncthreads();
        }
    }

    // result in buffer 1 (3 flips); emit first 512 columns
    {
        float4 v = *(const float4*)(sb + BF_STRIDE + ibf(t));
        out[(size_t)(row0 + 0)*HALFW + t] = v.x;
        out[(size_t)(row0 + 1)*HALFW + t] = v.y;
        out[(size_t)(row0 + 2)*HALFW + t] = v.z;
        out[(size_t)(row0 + 3)*HALFW + t] = v.w;
    }
}

extern "C" void kernel_launch(void* const* d_in, const int* in_sizes, int n_in,
                              void* d_out, int out_size)
{
    (void)in_sizes; (void)n_in; (void)out_size;
    const float* X          = (const float*)d_in[0];
    const float* scales     = (const float*)d_in[1];
    const float* angles     = (const float*)d_in[2];
    const float* act_bias   = (const float*)d_in[3];
    // d_in[4] = act_activation (unused by reference)
    const float* act_curv   = (const float*)d_in[5];
    const float* bf_angles  = (const float*)d_in[6];
    // d_in[7] = shuffle_perm (deterministic riffle, computed inline)
    const void*  recall_raw = d_in[8];
    const void*  out_raw    = d_in[9];
    // d_in[10] = bf_perm (deterministic riffle, computed inline)
    float* out = (float*)d_out;

    const int totalPrep = DEPTH_N*BDEPTH_N*HALFW + DEPTH_N*ACT_N;
    prep_kernel<<<(totalPrep + 255)/256, 256>>>(angles, act_bias, act_curv,
                                                recall_raw, out_raw);
    const int totalUnits = DEPTH_N*2*64 + 3*192;
    prep2_kernel<<<(totalUnits + 255)/256, 256>>>(angles, bf_angles);

    size_t smem = SMEM_FLOATS * sizeof(float);
    cudaFuncSetAttribute(sponge_kernel, cudaFuncAttributeMaxDynamicSharedMemorySize, (int)smem);
    sponge_kernel<<<NROWS/RROWS, NTHREADS, smem>>>(X, scales, out);
}